// round 8
// baseline (speedup 1.0000x reference)
#include <cuda_runtime.h>
#include <cuda_bf16.h>
#include <math.h>
#include <stdint.h>

// ---------------------------------------------------------------------------
// PowerIterationConv: sigma via Gram iteration in the DFT domain, grams on
// tensor cores via mma.sync m16n8k16 bf16 (fp32 accum), fragments via
// ldmatrix, operands pre-split to bf16 hi/lo planes in global memory.
//
//   Gr = R·R^T + I·I^T,  Gi = R·I^T − I·R^T  (G Hermitian every stage ->
//   6-of-9 64x64 tiles + conjugate mirror writes).  bf16 2-way split,
//   3 MMAs per real product (lo·lo dropped).
// ---------------------------------------------------------------------------

#define CDIM 192
#define MAT (CDIM*CDIM)
#define NW 145
#define NTOT2 289.0
#define SC2 48.0
#define NTILE 6
#define NPART (NTILE*NW)        // 870
#define F0BLK 256

#define KCH 96                  // k-chunk (2 chunks cover K=192)
#define SROW 104                // padded bf16 row stride (208B, conflict-free)
#define PL (64*SROW)            // plane elems (6656)
#define PLB (PL*2)              // plane bytes (13312)
#define SMEM_DYN (8*PLB)        // 106496 bytes

typedef unsigned int uint32;

// bf16 hi/lo planes, double-buffered across stages. plane: 0=Rh 1=Rl 2=Ih 3=Il
__device__ ushort g_pl[2][4][NW*MAT];
__device__ double g_f0sq;
__device__ double g_f0part[F0BLK];
__device__ double g_part[3][NPART];
__device__ double g_inv_sigma;
__device__ float2 g_phase[NW*9];

__device__ __forceinline__ uint32 smem_u32(const void* p) {
    uint32 a;
    asm("{ .reg .u64 t; cvta.to.shared.u64 t, %1; cvt.u32.u64 %0, t; }"
        : "=r"(a) : "l"(p));
    return a;
}
__device__ __forceinline__ void mma16816(float* d, const uint32* a,
                                         uint32 b0, uint32 b1) {
    asm volatile(
        "mma.sync.aligned.m16n8k16.row.col.f32.bf16.bf16.f32 "
        "{%0,%1,%2,%3}, {%4,%5,%6,%7}, {%8,%9}, {%0,%1,%2,%3};"
        : "+f"(d[0]), "+f"(d[1]), "+f"(d[2]), "+f"(d[3])
        : "r"(a[0]), "r"(a[1]), "r"(a[2]), "r"(a[3]), "r"(b0), "r"(b1));
}
__device__ __forceinline__ void ldm4(uint32* r, uint32 saddr) {
    asm volatile("ldmatrix.sync.aligned.m8n8.x4.shared.b16 {%0,%1,%2,%3}, [%4];"
        : "=r"(r[0]), "=r"(r[1]), "=r"(r[2]), "=r"(r[3]) : "r"(saddr));
}
__device__ __forceinline__ void split1(float v, ushort& h, ushort& l) {
    __nv_bfloat16 hb = __float2bfloat16(v);
    __nv_bfloat16 lb = __float2bfloat16(v - __bfloat162float(hb));
    h = __bfloat16_as_ushort(hb);
    l = __bfloat16_as_ushort(lb);
}

// ---- ||K0||_F^2 partials ---------------------------------------------------
__global__ void k_f0a(const float* __restrict__ K0, int n) {
    __shared__ double sred[256];
    int per = (n + F0BLK - 1) / F0BLK;
    int base = blockIdx.x * per;
    int end = min(base + per, n);
    double s = 0.0;
    for (int i = base + threadIdx.x; i < end; i += 256) {
        float v = K0[i];
        s += (double)v * (double)v;
    }
    sred[threadIdx.x] = s;
    __syncthreads();
    for (int off = 128; off > 0; off >>= 1) {
        if (threadIdx.x < off) sred[threadIdx.x] += sred[threadIdx.x + off];
        __syncthreads();
    }
    if (threadIdx.x == 0) g_f0part[blockIdx.x] = sred[0];
}

// ---- combine f0 + phase table ----------------------------------------------
__global__ void k_f0b() {
    __shared__ double sred[256];
    __shared__ double s_scale;
    sred[threadIdx.x] = g_f0part[threadIdx.x];
    __syncthreads();
    for (int off = 128; off > 0; off >>= 1) {
        if (threadIdx.x < off) sred[threadIdx.x] += sred[threadIdx.x + off];
        __syncthreads();
    }
    if (threadIdx.x == 0) {
        g_f0sq = sred[0];
        s_scale = sqrt(SC2 / sred[0]);
    }
    __syncthreads();
    double sc = s_scale;
    for (int idx = threadIdx.x; idx < NW * 9; idx += 256) {
        int w = idx / 9, s = idx % 9;
        int u, v;
        if (w == 0)      { u = 0; v = 0; }
        else if (w <= 8) { u = 0; v = w; }
        else             { u = 1 + (w - 9) / 17; v = (w - 9) % 17; }
        int y = s / 3, x = s % 3;
        int m = (u * y + v * x) % 17;
        double ang = -2.0 * 3.14159265358979323846 * (double)m / 17.0;
        g_phase[idx] = make_float2((float)(cos(ang) * sc), (float)(sin(ang) * sc));
    }
}

// ---- Build transposed DFT planes as bf16 hi/lo into buf 0 ------------------
__global__ void k_build(const float* __restrict__ K0) {
    int w = blockIdx.y;
    int ot = (blockIdx.x / 12) * 16;
    int at = (blockIdx.x % 12) * 16;
    __shared__ float2 ph[9];
    __shared__ float sre[16][17], sim[16][17];
    if (threadIdx.x < 9) ph[threadIdx.x] = g_phase[w * 9 + threadIdx.x];
    __syncthreads();
    int o_l = threadIdx.x >> 4, a_l = threadIdx.x & 15;
    const float* kp = K0 + ((ot + o_l) * CDIM + at + a_l) * 9;
    float re = 0.f, im = 0.f;
#pragma unroll
    for (int s = 0; s < 9; s++) {
        float k = kp[s];
        re = fmaf(k, ph[s].x, re);
        im = fmaf(k, ph[s].y, im);
    }
    sre[o_l][a_l] = re;
    sim[o_l][a_l] = im;
    __syncthreads();
    int a2 = threadIdx.x >> 4, o2 = threadIdx.x & 15;
    int dst = w * MAT + (at + a2) * CDIM + ot + o2;
    ushort h, l;
    split1(sre[o2][a2], h, l);
    g_pl[0][0][dst] = h;
    g_pl[0][1][dst] = l;
    split1(sim[o2][a2], h, l);
    g_pl[0][2][dst] = h;
    g_pl[0][3][dst] = l;
}

// ---- Tensor-core Hermitian gram --------------------------------------------
// grid (6, 145), block 256 (8 warps). Warps 0-3: Gr rows, 4-7: Gi rows.
// smem planes: A_{Rh,Rl,Ih,Il} (0-3), B_{Rh,Rl,Ih,Il} (4-7), 64 x 96 bf16
// each with SROW padding. Fragments via ldmatrix.x4.
__global__ void __launch_bounds__(256, 2) k_gram(int stage) {
    int sbuf = stage & 1;          // stage0:0 stage1:1 stage2:0
    int dbuf = sbuf ^ 1;
    const ushort* __restrict__ S0 = g_pl[sbuf][0];
    const ushort* __restrict__ S1 = g_pl[sbuf][1];
    const ushort* __restrict__ S2 = g_pl[sbuf][2];
    const ushort* __restrict__ S3 = g_pl[sbuf][3];

    int w = blockIdx.y;
    int t = blockIdx.x;            // (ai,bi): (0,0)(0,1)(0,2)(1,1)(1,2)(2,2)
    int ai, bi;
    if (t < 3)      { ai = 0; bi = t; }
    else if (t < 5) { ai = 1; bi = t - 2; }
    else            { ai = 2; bi = 2; }
    int a0g = ai * 64, b0g = bi * 64;

    extern __shared__ ushort sm16[];
    uint32 sbase = smem_u32(sm16);

    int tid = threadIdx.x;
    int wid = tid >> 5;
    int lane = tid & 31;
    int widx = wid & 3;
    bool isI = (wid >= 4);
    int mrow = widx * 16;
    int r  = lane >> 2;
    int cp = (lane & 3) * 2;

    float acc[8][4];
#pragma unroll
    for (int nt = 0; nt < 8; nt++)
#pragma unroll
        for (int q = 0; q < 4; q++) acc[nt][q] = 0.f;

    // lane-invariant ldmatrix byte offsets
    int aoff = 2 * ((mrow + (lane & 7) + ((lane >> 3) & 1) * 8) * SROW +
                    (lane >> 4) * 8);
    int boff = 2 * (((lane >> 4) * 8 + (lane & 7)) * SROW +
                    ((lane >> 3) & 1) * 8);

    uint32 aRh = sbase + 0 * PLB, aRl = sbase + 1 * PLB;
    uint32 aIh = sbase + 2 * PLB, aIl = sbase + 3 * PLB;
    uint32 bxh = sbase + (isI ? 6 : 4) * PLB;   // Dr: B_Rh ; Di: B_Ih
    uint32 bxl = sbase + (isI ? 7 : 5) * PLB;
    uint32 byh = sbase + (isI ? 4 : 6) * PLB;   // Dr: B_Ih ; Di: B_Rh
    uint32 byl = sbase + (isI ? 5 : 7) * PLB;

    for (int c = 0; c < 2; c++) {
        int kb = c * KCH;
        // pure copy load: 4 planes x 128 rows (64 A + 64 B) x 12 x 16B
        for (int s = tid; s < 4 * 128 * 12; s += 256) {
            int p = s / (128 * 12);
            int rem = s % (128 * 12);
            int row = rem / 12;
            int seg = rem % 12;
            int grow = (row < 64) ? (a0g + row) : (b0g + row - 64);
            const ushort* sp = (p == 0) ? S0 : (p == 1) ? S1 : (p == 2) ? S2 : S3;
            uint4 v = *(const uint4*)&sp[w * MAT + grow * CDIM + kb + seg * 8];
            int pl = p + ((row < 64) ? 0 : 4);
            *(uint4*)&sm16[pl * PL + (row & 63) * SROW + seg * 8] = v;
        }
        __syncthreads();

#pragma unroll 1
        for (int ks = 0; ks < 6; ks++) {
            int k0b = ks * 32;            // 16 bf16 = 32 bytes
            uint32 fRh[4], fRl[4], fIh[4], fIl[4];
            ldm4(fRh, aRh + aoff + k0b);
            ldm4(fRl, aRl + aoff + k0b);
            ldm4(fIh, aIh + aoff + k0b);
            ldm4(fIl, aIl + aoff + k0b);
            if (isI) {    // Di = R·I^T + (−I)·R^T
#pragma unroll
                for (int q = 0; q < 4; q++) {
                    fIh[q] ^= 0x80008000u;
                    fIl[q] ^= 0x80008000u;
                }
            }
#pragma unroll
            for (int np = 0; np < 4; np++) {
                int bo = boff + np * (16 * SROW * 2) + k0b;
                uint32 xh[4], xl[4], yh[4], yl[4];
                ldm4(xh, bxh + bo);
                ldm4(xl, bxl + bo);
                ldm4(yh, byh + bo);
                ldm4(yl, byl + bo);
                int nt = np * 2;
                mma16816(acc[nt], fRh, xh[0], xh[1]);
                mma16816(acc[nt], fRh, xl[0], xl[1]);
                mma16816(acc[nt], fRl, xh[0], xh[1]);
                mma16816(acc[nt], fIh, yh[0], yh[1]);
                mma16816(acc[nt], fIh, yl[0], yl[1]);
                mma16816(acc[nt], fIl, yh[0], yh[1]);
                mma16816(acc[nt + 1], fRh, xh[2], xh[3]);
                mma16816(acc[nt + 1], fRh, xl[2], xl[3]);
                mma16816(acc[nt + 1], fRl, xh[2], xh[3]);
                mma16816(acc[nt + 1], fIh, yh[2], yh[3]);
                mma16816(acc[nt + 1], fIh, yl[2], yl[3]);
                mma16816(acc[nt + 1], fIl, yh[2], yh[3]);
            }
        }
        __syncthreads();
    }

    // ---- epilogue: split to bf16 hi/lo dst planes (+ conj mirror), norms ----
    bool offdiag = (ai != bi);
    bool wr = (stage != 2);
    ushort* DH = g_pl[dbuf][isI ? 2 : 0] + w * MAT;
    ushort* DL = g_pl[dbuf][isI ? 3 : 1] + w * MAT;
    ushort sgnm = isI ? 0x8000 : 0;
    float ns = 0.f;
#pragma unroll
    for (int nt = 0; nt < 8; nt++) {
        float v0 = acc[nt][0], v1 = acc[nt][1];
        float v2 = acc[nt][2], v3 = acc[nt][3];
        ns = fmaf(v0, v0, ns); ns = fmaf(v1, v1, ns);
        ns = fmaf(v2, v2, ns); ns = fmaf(v3, v3, ns);
        if (wr) {
            int gr0 = a0g + mrow + r;
            int gc0 = b0g + nt * 8 + cp;
            ushort h0, l0, h1, l1, h2, l2, h3, l3;
            split1(v0, h0, l0); split1(v1, h1, l1);
            split1(v2, h2, l2); split1(v3, h3, l3);
            *(uint32*)&DH[gr0 * CDIM + gc0] = (uint32)h0 | ((uint32)h1 << 16);
            *(uint32*)&DL[gr0 * CDIM + gc0] = (uint32)l0 | ((uint32)l1 << 16);
            *(uint32*)&DH[(gr0 + 8) * CDIM + gc0] = (uint32)h2 | ((uint32)h3 << 16);
            *(uint32*)&DL[(gr0 + 8) * CDIM + gc0] = (uint32)l2 | ((uint32)l3 << 16);
            if (offdiag) {
                DH[gc0 * CDIM + gr0]           = h0 ^ sgnm;
                DL[gc0 * CDIM + gr0]           = l0 ^ sgnm;
                DH[(gc0 + 1) * CDIM + gr0]     = h1 ^ sgnm;
                DL[(gc0 + 1) * CDIM + gr0]     = l1 ^ sgnm;
                DH[gc0 * CDIM + gr0 + 8]       = h2 ^ sgnm;
                DL[gc0 * CDIM + gr0 + 8]       = l2 ^ sgnm;
                DH[(gc0 + 1) * CDIM + gr0 + 8] = h3 ^ sgnm;
                DL[(gc0 + 1) * CDIM + gr0 + 8] = l3 ^ sgnm;
            }
        }
    }

    double* red = (double*)sm16;     // planes dead
    red[tid] = (double)ns;
    __syncthreads();
    for (int off = 128; off > 0; off >>= 1) {
        if (tid < off) red[tid] += red[tid + off];
        __syncthreads();
    }
    if (tid == 0) {
        double wgt = ((w == 0) ? 1.0 : 2.0) * (offdiag ? 2.0 : 1.0);
        g_part[stage][w * NTILE + t] = wgt * red[0];
    }
}

// ---- Deterministic final reduction + sigma ---------------------------------
__global__ void k_sigma() {
    __shared__ double sred[256];
    double m[3];
    for (int s = 0; s < 3; s++) {
        double acc = 0.0;
        for (int i = threadIdx.x; i < NPART; i += 256) acc += g_part[s][i];
        sred[threadIdx.x] = acc;
        __syncthreads();
        for (int off = 128; off > 0; off >>= 1) {
            if (threadIdx.x < off) sred[threadIdx.x] += sred[threadIdx.x + off];
            __syncthreads();
        }
        m[s] = sred[0];
        __syncthreads();
    }
    if (threadIdx.x == 0) {
        double f0 = sqrt(g_f0sq);
        double f1 = sqrt(m[0] / NTOT2) / SC2;
        double f2 = sqrt(m[1] / NTOT2) / (SC2 * SC2 * f1 * f1);
        double ff = sqrt(m[2] / NTOT2) /
                    (SC2 * SC2 * SC2 * SC2 * f1 * f1 * f1 * f1 * f2 * f2);
        double logs = log(f0) + 0.5 * log(f1) + 0.25 * log(f2) + 0.125 * log(ff);
        g_inv_sigma = exp(-logs);
    }
}

__global__ void k_scale(const float* __restrict__ K0, float* __restrict__ out,
                        int n) {
    float s = (float)g_inv_sigma;
    int i = blockIdx.x * 256 + threadIdx.x;
    if (i < n) out[i] = K0[i] * s;
}

extern "C" void kernel_launch(void* const* d_in, const int* in_sizes, int n_in,
                              void* d_out, int out_size) {
    const float* K0 = (const float*)d_in[0];
    float* out = (float*)d_out;
    int n = in_sizes[0];   // 331776

    cudaFuncSetAttribute(k_gram, cudaFuncAttributeMaxDynamicSharedMemorySize,
                         SMEM_DYN);

    k_f0a<<<F0BLK, 256>>>(K0, n);
    k_f0b<<<1, 256>>>();
    k_build<<<dim3(144, NW), 256>>>(K0);
    k_gram<<<dim3(NTILE, NW), 256, SMEM_DYN>>>(0);
    k_gram<<<dim3(NTILE, NW), 256, SMEM_DYN>>>(1);
    k_gram<<<dim3(NTILE, NW), 256, SMEM_DYN>>>(2);
    k_sigma<<<1, 256>>>();
    k_scale<<<(n + 255) / 256, 256>>>(K0, out, n);
}